// round 12
// baseline (speedup 1.0000x reference)
#include <cuda_runtime.h>

#define NPOS        22743
#define NB          64
#define CELLS_PER_B 7581                    // 76*76 + 38*38 + 19*19
#define TOTAL_CELLS (NB * CELLS_PER_B)      // 485184
#define BLK         256
#define CHUNK       10                      // cells per warp-iteration (lanes 0..29)
#define NCHUNKS     ((TOTAL_CELLS + CHUNK - 1) / CHUNK)   // 48519
#define GRID_BLKS   1184                    // 148 SMs x 8

// Accumulators: [0]=n_obj  [1]=s_xy  [2]=s_wh  [3]=s_cls  [4]=s_obj(weighted)
__device__ float        g_acc[5];
__device__ unsigned int g_cnt;
__device__ unsigned int g_work;             // chunk counter (reset by finalizer)

// ANCHORS / stride, stride = 608/grid = {8,16,32} (exact in fp32)
__constant__ float c_anch[3][3][2] = {
    {{1.25f, 1.625f},  {2.0f,   3.75f},   {4.125f,    2.875f}},
    {{1.875f,2.8125f}, {3.875f, 2.8125f}, {3.6875f,   7.4375f}},
    {{3.625f,2.8125f}, {4.875f, 6.1875f}, {11.65625f, 10.1875f}},
};

// bce(sigmoid(z), t) = softplus(z) - t*z
__device__ __forceinline__ float softplusf(float z) {
    return __logf(1.0f + __expf(z));
}

__global__ void __launch_bounds__(BLK)
yolo_loss_kernel(const float* __restrict__ x, const float* __restrict__ t,
                 float* __restrict__ out) {
    const int lane = threadIdx.x & 31;
    const unsigned FULL = 0xFFFFFFFFu;

    // lane -> (cell-in-chunk, anchor j); lanes 30,31 idle
    const int cw = lane / 3;                 // 0..10 (10 for lanes 30,31)
    const int j  = lane - cw * 3;            // 0..2
    const int lb = cw * 3;                   // base lane of my triple

    float a_n = 0.f, a_xy = 0.f, a_wh = 0.f, a_cls = 0.f, a_obj = 0.f;

    // warp-autonomous work stealing
    unsigned chunk;
    if (lane == 0) chunk = atomicAdd(&g_work, 1u);
    chunk = __shfl_sync(FULL, chunk, 0);

    while (chunk < NCHUNKS) {
        const int gcell  = (int)chunk * CHUNK + cw;
        const bool active = (lane < 30) && (gcell < TOTAL_CELLS);

        float inter = 0.f, d = 1.f;
        float t2r = 0.f, t3r = 0.f, t4v = 0.f, x4v = 0.f;
        size_t off = 0;
        float wobj = 0.f;

        if (active) {
            const int b    = gcell / CELLS_PER_B;     // const-divide -> mul.hi
            const int cell = gcell - b * CELLS_PER_B;

            int sc, p0;
            float g;
            if (cell < 5776) {                    // 76x76
                sc = 0; p0 = cell * 3;                     g = 76.f; wobj = 1.f / 1108992.f;
            } else if (cell < 7220) {             // 38x38
                sc = 1; p0 = 17328 + (cell - 5776) * 3;    g = 38.f; wobj = 1.f / 277248.f;
            } else {                              // 19x19
                sc = 2; p0 = 21660 + (cell - 7220) * 3;    g = 19.f; wobj = 1.f / 69312.f;
            }

            off = ((size_t)b * NPOS + p0 + j) * 85;

            // 4 front-batched loads
            t2r = __ldg(t + off + 2);
            t3r = __ldg(t + off + 3);
            t4v = __ldg(t + off + 4);
            x4v = __ldg(x + off + 4);

            float tw = t2r * g, th = t3r * g;
            float aw = c_anch[sc][j][0], ah = c_anch[sc][j][1];
            float in_ = fminf(tw, aw) * fminf(th, ah);
            inter = in_;
            d     = tw * th + aw * ah - in_ + 1e-12f;   // union + eps, > 0
        }

        // fetch next chunk early — overlaps the L2 atomic with compute below
        unsigned nchunk;
        if (lane == 0) nchunk = atomicAdd(&g_work, 1u);

        // argmax of inter/d across the 3 lanes of this cell (cross-mult, d > 0),
        // first-occurrence tie-break. All lanes participate in shuffles.
        float i0 = __shfl_sync(FULL, inter, lb);
        float i1 = __shfl_sync(FULL, inter, lb + 1);
        float i2 = __shfl_sync(FULL, inter, lb + 2);
        float d0 = __shfl_sync(FULL, d, lb);
        float d1 = __shfl_sync(FULL, d, lb + 1);
        float d2 = __shfl_sync(FULL, d, lb + 2);

        if (active) {
            int best = 0;
            float ib = i0, db = d0;
            if (i1 * db > ib * d1) { best = 1; ib = i1; db = d1; }
            if (i2 * db > ib * d2) { best = 2; }

            bool keep = (inter <= 0.7f * d) || (j == best);

            // s = bce(sigmoid(x4), t4) = softplus(x4) - t4*x4
            float s = softplusf(x4v) - t4v * x4v;

            // obj: keep ? s : bce(sigmoid(0), 0) = ln 2
            a_obj += wobj * (keep ? s : 0.69314718055994531f);

            if (t4v > 0.0f) {                 // ~2% of positions
                a_n   += 1.0f;
                a_cls += s;

                float x0 = __ldg(x + off + 0), x1 = __ldg(x + off + 1);
                float x2 = __ldg(x + off + 2), x3 = __ldg(x + off + 3);
                float t0 = __ldg(t + off + 0), t1 = __ldg(t + off + 1);

                // xy: bce(sigmoid(x), t)
                a_xy += (softplusf(x0) - t0 * x0) + (softplusf(x1) - t1 * x1);

                // wh: bce(clip(x, eps, 1-eps), t)  [1-eps rounds to 1.0f in fp32]
                float p2 = fmaxf(x2, 1e-12f);
                float p3 = fmaxf(x3, 1e-12f);
                a_wh += -(t2r * __logf(p2) + (1.0f - t2r) * __logf(1.0f - p2));
                a_wh += -(t3r * __logf(p3) + (1.0f - t3r) * __logf(1.0f - p3));
            }
        }

        chunk = __shfl_sync(FULL, nchunk, 0);
    }

    // ---- reduction: warp shuffle -> shared -> global atomics ----
    #pragma unroll
    for (int o = 16; o > 0; o >>= 1) {
        a_n   += __shfl_down_sync(FULL, a_n,   o);
        a_xy  += __shfl_down_sync(FULL, a_xy,  o);
        a_wh  += __shfl_down_sync(FULL, a_wh,  o);
        a_cls += __shfl_down_sync(FULL, a_cls, o);
        a_obj += __shfl_down_sync(FULL, a_obj, o);
    }

    __shared__ float sh[5];
    if (threadIdx.x < 5) sh[threadIdx.x] = 0.0f;
    __syncthreads();
    if ((threadIdx.x & 31) == 0) {
        atomicAdd(&sh[0], a_n);
        atomicAdd(&sh[1], a_xy);
        atomicAdd(&sh[2], a_wh);
        atomicAdd(&sh[3], a_cls);
        atomicAdd(&sh[4], a_obj);
    }
    __syncthreads();
    if (threadIdx.x < 5) atomicAdd(&g_acc[threadIdx.x], sh[threadIdx.x]);

    // ---- last block finalizes and resets state for the next graph replay ----
    if (threadIdx.x == 0) {
        __threadfence();
        unsigned int done = atomicAdd(&g_cnt, 1u);
        if (done == GRID_BLKS - 1) {
            float vn   = atomicAdd(&g_acc[0], 0.f);
            float vxy  = atomicAdd(&g_acc[1], 0.f);
            float vwh  = atomicAdd(&g_acc[2], 0.f);
            float vcls = atomicAdd(&g_acc[3], 0.f);
            float vobj = atomicAdd(&g_acc[4], 0.f);
            float n = fmaxf(vn, 1.0f);
            out[0] = (vxy + vwh) / (2.0f * n) + vcls / n + vobj;
            atomicExch(&g_acc[0], 0.f);
            atomicExch(&g_acc[1], 0.f);
            atomicExch(&g_acc[2], 0.f);
            atomicExch(&g_acc[3], 0.f);
            atomicExch(&g_acc[4], 0.f);
            atomicExch(&g_work, 0u);
            atomicExch(&g_cnt, 0u);
        }
    }
}

extern "C" void kernel_launch(void* const* d_in, const int* in_sizes, int n_in,
                              void* d_out, int out_size) {
    const float* x = (const float*)d_in[0];
    const float* t = (const float*)d_in[1];
    float* out = (float*)d_out;

    yolo_loss_kernel<<<GRID_BLKS, BLK>>>(x, t, out);
}

// round 13
// speedup vs baseline: 2.3036x; 2.3036x over previous
#include <cuda_runtime.h>

#define NPOS        22743
#define NB          64
#define CELLS_PER_B 7581            // 76*76 + 38*38 + 19*19
#define BLK         512
#define WARPS_PB    16
#define CELLS_PW    10              // lanes 0..29 = 10 cells x 3 anchors
#define BX          48              // 48*16*10 = 7680 >= 7581 cells
#define TOTAL_BLOCKS (BX * NB)      // 3072

// Accumulators: [0]=n_obj  [1]=s_xy  [2]=s_wh  [3]=s_cls  [4]=s_obj(weighted)
__device__ float        g_acc[5];
__device__ unsigned int g_cnt;

// ANCHORS / stride, stride = 608/grid = {8,16,32} (exact in fp32)
__constant__ float c_anch[3][3][2] = {
    {{1.25f, 1.625f},  {2.0f,   3.75f},   {4.125f,    2.875f}},
    {{1.875f,2.8125f}, {3.875f, 2.8125f}, {3.6875f,   7.4375f}},
    {{3.625f,2.8125f}, {4.875f, 6.1875f}, {11.65625f, 10.1875f}},
};

// bce(sigmoid(z), t) = softplus(z) - t*z
__device__ __forceinline__ float softplusf(float z) {
    return __logf(1.0f + __expf(z));
}

__global__ void __launch_bounds__(BLK, 4)
yolo_loss_kernel(const float* __restrict__ x, const float* __restrict__ t,
                 float* __restrict__ out) {
    const int lane = threadIdx.x & 31;
    const int wInB = threadIdx.x >> 5;
    const int b    = blockIdx.y;

    // lane -> (cell-in-warp, anchor j); lanes 30,31 idle
    const int cw   = lane / 3;               // 0..10 (10 for lanes 30,31)
    const int j    = lane - cw * 3;          // 0..2
    const int cell = (blockIdx.x * WARPS_PB + wInB) * CELLS_PW + cw;
    const bool active = (lane < 30) && (cell < CELLS_PER_B);

    float a_n = 0.f, a_xy = 0.f, a_wh = 0.f, a_cls = 0.f, a_obj = 0.f;

    // defaults so idle lanes shuffle defined values
    float inter = 0.f, d = 1.f;
    float t2r = 0.f, t3r = 0.f, t4v = 0.f, x4v = 0.f;
    size_t off = 0;
    float wobj = 0.f;

    if (active) {
        int sc, p0;
        float g;
        if (cell < 5776) {                    // 76x76
            sc = 0; p0 = cell * 3;                     g = 76.f; wobj = 1.f / 1108992.f;
        } else if (cell < 7220) {             // 38x38
            sc = 1; p0 = 17328 + (cell - 5776) * 3;    g = 38.f; wobj = 1.f / 277248.f;
        } else {                              // 19x19
            sc = 2; p0 = 21660 + (cell - 7220) * 3;    g = 19.f; wobj = 1.f / 69312.f;
        }

        off = ((size_t)b * NPOS + p0 + j) * 85;

        // 4 front-batched loads, MLP_p1 = 4
        t2r = __ldg(t + off + 2);
        t3r = __ldg(t + off + 3);
        t4v = __ldg(t + off + 4);
        x4v = __ldg(x + off + 4);

        float tw = t2r * g, th = t3r * g;
        float aw = c_anch[sc][j][0], ah = c_anch[sc][j][1];
        float in_ = fminf(tw, aw) * fminf(th, ah);
        inter = in_;
        d     = tw * th + aw * ah - in_ + 1e-12f;   // union + eps, > 0
    }

    // argmax of inter/d across the 3 lanes of this cell (cross-mult, d > 0),
    // first-occurrence tie-break. All lanes participate in shuffles.
    const int lb = cw * 3;                    // base lane of my triple (30 for idles)
    const unsigned FULL = 0xFFFFFFFFu;
    float i0 = __shfl_sync(FULL, inter, lb);
    float i1 = __shfl_sync(FULL, inter, lb + 1);
    float i2 = __shfl_sync(FULL, inter, lb + 2);
    float d0 = __shfl_sync(FULL, d, lb);
    float d1 = __shfl_sync(FULL, d, lb + 1);
    float d2 = __shfl_sync(FULL, d, lb + 2);

    if (active) {
        int best = 0;
        float ib = i0, db = d0;
        if (i1 * db > ib * d1) { best = 1; ib = i1; db = d1; }
        if (i2 * db > ib * d2) { best = 2; }

        bool keep = (inter <= 0.7f * d) || (j == best);

        // s = bce(sigmoid(x4), t4) = softplus(x4) - t4*x4
        float s = softplusf(x4v) - t4v * x4v;

        // obj: keep ? s : bce(sigmoid(0), 0) = ln 2
        a_obj = wobj * (keep ? s : 0.69314718055994531f);

        if (t4v > 0.0f) {                     // ~2% of positions
            a_n   = 1.0f;
            a_cls = s;

            float x0 = __ldg(x + off + 0), x1 = __ldg(x + off + 1);
            float x2 = __ldg(x + off + 2), x3 = __ldg(x + off + 3);
            float t0 = __ldg(t + off + 0), t1 = __ldg(t + off + 1);

            // xy: bce(sigmoid(x), t)
            a_xy = (softplusf(x0) - t0 * x0) + (softplusf(x1) - t1 * x1);

            // wh: bce(clip(x, eps, 1-eps), t)  [1-eps rounds to 1.0f in fp32]
            float p2 = fmaxf(x2, 1e-12f);
            float p3 = fmaxf(x3, 1e-12f);
            a_wh  = -(t2r * __logf(p2) + (1.0f - t2r) * __logf(1.0f - p2))
                    -(t3r * __logf(p3) + (1.0f - t3r) * __logf(1.0f - p3));
        }
    }

    // ---- reduction: warp shuffle -> shared -> global atomics ----
    #pragma unroll
    for (int o = 16; o > 0; o >>= 1) {
        a_n   += __shfl_down_sync(FULL, a_n,   o);
        a_xy  += __shfl_down_sync(FULL, a_xy,  o);
        a_wh  += __shfl_down_sync(FULL, a_wh,  o);
        a_cls += __shfl_down_sync(FULL, a_cls, o);
        a_obj += __shfl_down_sync(FULL, a_obj, o);
    }

    __shared__ float sh[5];
    if (threadIdx.x < 5) sh[threadIdx.x] = 0.0f;
    __syncthreads();
    if ((threadIdx.x & 31) == 0) {
        atomicAdd(&sh[0], a_n);
        atomicAdd(&sh[1], a_xy);
        atomicAdd(&sh[2], a_wh);
        atomicAdd(&sh[3], a_cls);
        atomicAdd(&sh[4], a_obj);
    }
    __syncthreads();
    if (threadIdx.x < 5) atomicAdd(&g_acc[threadIdx.x], sh[threadIdx.x]);

    // ---- last block finalizes and resets state for the next graph replay ----
    if (threadIdx.x == 0) {
        __threadfence();
        unsigned int done = atomicAdd(&g_cnt, 1u);
        if (done == TOTAL_BLOCKS - 1) {
            float vn   = atomicAdd(&g_acc[0], 0.f);
            float vxy  = atomicAdd(&g_acc[1], 0.f);
            float vwh  = atomicAdd(&g_acc[2], 0.f);
            float vcls = atomicAdd(&g_acc[3], 0.f);
            float vobj = atomicAdd(&g_acc[4], 0.f);
            float n = fmaxf(vn, 1.0f);
            out[0] = (vxy + vwh) / (2.0f * n) + vcls / n + vobj;
            atomicExch(&g_acc[0], 0.f);
            atomicExch(&g_acc[1], 0.f);
            atomicExch(&g_acc[2], 0.f);
            atomicExch(&g_acc[3], 0.f);
            atomicExch(&g_acc[4], 0.f);
            atomicExch(&g_cnt, 0u);
        }
    }
}

extern "C" void kernel_launch(void* const* d_in, const int* in_sizes, int n_in,
                              void* d_out, int out_size) {
    const float* x = (const float*)d_in[0];
    const float* t = (const float*)d_in[1];
    float* out = (float*)d_out;

    dim3 grid(BX, NB);
    yolo_loss_kernel<<<grid, BLK>>>(x, t, out);
}